// round 4
// baseline (speedup 1.0000x reference)
#include <cuda_runtime.h>
#include <stdint.h>
#include <math.h>

#define NMAX 50000
#define EMAX 800000

// ---------------- scratch (static __device__ — no allocation) ----------------
__device__ float g_z[(size_t)NMAX * 128];      // per-head projections [N, H*O]
__device__ float g_el[(size_t)NMAX * 8];       // a_l . z  [N,H]
__device__ float g_er[(size_t)NMAX * 8];       // a_r . z  [N,H]
__device__ float g_h[(size_t)NMAX * 128];      // elu(gat)+x  [N,D]
__device__ float g_lnv[(size_t)NMAX * 128];    // layernorm(h)
__device__ float g_inter[(size_t)NMAX * 512];  // gelu(ln@w1+b1)
__device__ int   g_cnt[NMAX];
__device__ int   g_off[NMAX + 1];
__device__ int   g_cur[NMAX];
__device__ int   g_csrc[EMAX];

// ---------------- f32x2 packed-FMA helpers (SASS FFMA2) ----------------
__device__ __forceinline__ unsigned long long pack2(float x) {
    unsigned long long r;
    unsigned xi = __float_as_uint(x);
    asm("mov.b64 %0, {%1, %1};" : "=l"(r) : "r"(xi));
    return r;
}
__device__ __forceinline__ void fma2(unsigned long long& acc,
                                     unsigned long long a, unsigned long long b) {
    asm("fma.rn.f32x2 %0, %1, %2, %0;" : "+l"(acc) : "l"(a), "l"(b));
}
__device__ __forceinline__ float2 unpack2(unsigned long long v) {
    unsigned lo, hi;
    asm("mov.b64 {%0, %1}, %2;" : "=r"(lo), "=r"(hi) : "l"(v));
    return make_float2(__uint_as_float(lo), __uint_as_float(hi));
}
__device__ __forceinline__ float gelu_exact(float v) {
    return 0.5f * v * (1.0f + erff(v * 0.70710678118654752440f));
}

// =====================================================================
// Register-tiled GEMM: C[M,N] = A[M,KTOT] @ B[KTOT,N]
// BM=BN=128, BK=16, 256 threads (16x16), 8x8 outputs per thread
// (split 4+4 rows / 4+4 cols for conflict-free LDS.128).
// EPI: 0 = proj (B gathered from fc_w, out=g_z)
//      1 = ffn1 (gelu(acc+bias) -> g_inter, N=512)
//      2 = ffn2 (acc+bias+res -> out, N=128)
// =====================================================================
template<int KTOT, int EPI>
__global__ __launch_bounds__(256) void gemm_kernel(
    const float* __restrict__ A, const float* __restrict__ B,
    const float* __restrict__ bias, const float* __restrict__ res,
    float* __restrict__ out, int M)
{
    constexpr int NTOT = (EPI == 1) ? 512 : 128;
    __shared__ float As[16 * 132];   // k-major, stride 132 (16B aligned, conflict-spread)
    __shared__ float Bs[16 * 128];   // row-major [k][col]

    const int t  = threadIdx.x;
    const int tx = t & 15, ty = t >> 4;
    const int row0 = blockIdx.x * 128;
    const int col0 = blockIdx.y * 128;

    unsigned long long acc[8][4];
#pragma unroll
    for (int r = 0; r < 8; r++)
#pragma unroll
        for (int p = 0; p < 4; p++) acc[r][p] = 0ull;

    const float4* A4 = (const float4*)A;
    const float4* B4 = (const float4*)B;

#pragma unroll 1
    for (int k0 = 0; k0 < KTOT; k0 += 16) {
        // ---- load A tile [128 rows x 16 k], transposed to As[k][row] ----
#pragma unroll
        for (int i = 0; i < 2; i++) {
            int row = (t >> 2) + i * 64;
            int c4  = t & 3;
            int grow = row0 + row;
            float4 v = make_float4(0.f, 0.f, 0.f, 0.f);
            if (grow < M) v = A4[grow * (KTOT >> 2) + (k0 >> 2) + c4];
            As[(c4 * 4 + 0) * 132 + row] = v.x;
            As[(c4 * 4 + 1) * 132 + row] = v.y;
            As[(c4 * 4 + 2) * 132 + row] = v.z;
            As[(c4 * 4 + 3) * 132 + row] = v.w;
        }
        // ---- load B tile [16 k x 128 cols] ----
        if (EPI == 0) {
            // B[k][n] = fc_w[n>>4][k][n&15], fc_w strides (2048,16,1)
#pragma unroll
            for (int i = 0; i < 8; i++) {
                int idx = t + i * 256;
                int kk = idx >> 7, col = idx & 127;
                Bs[kk * 128 + col] = B[(col >> 4) * 2048 + (k0 + kk) * 16 + (col & 15)];
            }
        } else {
#pragma unroll
            for (int i = 0; i < 2; i++) {
                int kk = t >> 4;
                int c4 = (t & 15) + i * 16;
                float4 v = B4[(size_t)(k0 + kk) * (NTOT >> 2) + (col0 >> 2) + c4];
                ((float4*)Bs)[kk * 32 + c4] = v;
            }
        }
        __syncthreads();

#pragma unroll
        for (int kk = 0; kk < 16; kk++) {
            float4 a0 = *(const float4*)&As[kk * 132 + ty * 4];
            float4 a1 = *(const float4*)&As[kk * 132 + 64 + ty * 4];
            ulonglong2 b0 = *(const ulonglong2*)&Bs[kk * 128 + tx * 4];
            ulonglong2 b1 = *(const ulonglong2*)&Bs[kk * 128 + 64 + tx * 4];
            float av[8] = {a0.x, a0.y, a0.z, a0.w, a1.x, a1.y, a1.z, a1.w};
#pragma unroll
            for (int r = 0; r < 8; r++) {
                unsigned long long pa = pack2(av[r]);
                fma2(acc[r][0], pa, b0.x);
                fma2(acc[r][1], pa, b0.y);
                fma2(acc[r][2], pa, b1.x);
                fma2(acc[r][3], pa, b1.y);
            }
        }
        __syncthreads();
    }

    // ---- epilogue ----
#pragma unroll
    for (int r = 0; r < 8; r++) {
        int row = row0 + ((r < 4) ? (ty * 4 + r) : (64 + ty * 4 + r - 4));
        if (row >= M) continue;
#pragma unroll
        for (int p = 0; p < 4; p++) {
            float2 v = unpack2(acc[r][p]);
            int lcol = (p < 2) ? (tx * 4 + 2 * p) : (64 + tx * 4 + 2 * (p - 2));
            int col = col0 + lcol;
            if (EPI == 0) {
                *(float2*)&out[(size_t)row * 128 + col] = v;
            } else if (EPI == 1) {
                v.x = gelu_exact(v.x + bias[col]);
                v.y = gelu_exact(v.y + bias[col + 1]);
                *(float2*)&out[(size_t)row * 512 + col] = v;
            } else {
                v.x += bias[col] + res[(size_t)row * 128 + col];
                v.y += bias[col + 1] + res[(size_t)row * 128 + col + 1];
                *(float2*)&out[(size_t)row * 128 + col] = v;
            }
        }
    }
}

// =====================================================================
// el/er epilogue: warp per node. lane l covers dims l*4..l*4+3 (head l>>2).
// =====================================================================
__global__ __launch_bounds__(256) void eler_kernel(
    const float* __restrict__ a_l, const float* __restrict__ a_r, int n)
{
    int warp = (blockIdx.x * blockDim.x + threadIdx.x) >> 5;
    int lane = threadIdx.x & 31;
    if (warp >= n) return;
    float4 z = ((const float4*)g_z)[(size_t)warp * 32 + lane];
    float4 al = ((const float4*)a_l)[lane];
    float4 ar = ((const float4*)a_r)[lane];
    float sl = z.x * al.x + z.y * al.y + z.z * al.z + z.w * al.w;
    float sr = z.x * ar.x + z.y * ar.y + z.z * ar.z + z.w * ar.w;
    sl += __shfl_xor_sync(0xffffffffu, sl, 1);
    sl += __shfl_xor_sync(0xffffffffu, sl, 2);
    sr += __shfl_xor_sync(0xffffffffu, sr, 1);
    sr += __shfl_xor_sync(0xffffffffu, sr, 2);
    if ((lane & 3) == 0) {
        int head = lane >> 2;
        g_el[warp * 8 + head] = sl;
        g_er[warp * 8 + head] = sr;
    }
}

// =====================================================================
// CSR build
// =====================================================================
__global__ void zero_cnt_kernel(int n) {
    int i = blockIdx.x * blockDim.x + threadIdx.x;
    if (i < n) g_cnt[i] = 0;
}

__global__ void hist_kernel(const int* __restrict__ dst, int E) {
    int i = blockIdx.x * blockDim.x + threadIdx.x;
    if (i < E) atomicAdd(&g_cnt[dst[i]], 1);
}

__global__ __launch_bounds__(1024) void scan_kernel(int n) {
    int t = threadIdx.x;
    int chunk = (n + 1023) >> 10;
    int b = t * chunk;
    int e = b + chunk; if (e > n) e = n;
    int s = 0;
    for (int i = b; i < e; i++) s += g_cnt[i];
    int own = s;
    int lane = t & 31, w = t >> 5;
#pragma unroll
    for (int d = 1; d < 32; d <<= 1) {
        int v = __shfl_up_sync(0xffffffffu, s, d);
        if (lane >= d) s += v;
    }
    __shared__ int ws[32];
    if (lane == 31) ws[w] = s;
    __syncthreads();
    if (w == 0) {
        int v = ws[lane];
#pragma unroll
        for (int d = 1; d < 32; d <<= 1) {
            int u = __shfl_up_sync(0xffffffffu, v, d);
            if (lane >= d) v += u;
        }
        ws[lane] = v;
    }
    __syncthreads();
    int run = s - own + (w ? ws[w - 1] : 0);
    for (int i = b; i < e; i++) {
        g_off[i] = run;
        g_cur[i] = run;
        run += g_cnt[i];
    }
    if (t == 1023) g_off[n] = ws[31];
}

__global__ void scatter_kernel(const int* __restrict__ src, const int* __restrict__ dst, int E) {
    int i = blockIdx.x * blockDim.x + threadIdx.x;
    if (i < E) {
        int d = dst[i];
        int p = atomicAdd(&g_cur[d], 1);
        g_csrc[p] = src[i];
    }
}

// =====================================================================
// GAT: per-dst softmax + aggregation + elu + residual + fused LayerNorm
// One warp per dst node.
// =====================================================================
__global__ __launch_bounds__(256) void gat_ln_kernel(
    const float* __restrict__ x,
    const float* __restrict__ gg, const float* __restrict__ bb, int n)
{
    int warp = (blockIdx.x * blockDim.x + threadIdx.x) >> 5;
    int lane = threadIdx.x & 31;
    if (warp >= n) return;
    int d = warp;
    int beg = g_off[d], end = g_off[d + 1];

    int h1 = lane & 7, eo = lane >> 3;
    float er_a = g_er[d * 8 + h1];

    // pass 1: per-head denominator (4 edges x 8 heads per step)
    float denom = 0.f;
    int iters = (end - beg + 3) >> 2;
    for (int it = 0; it < iters; it++) {
        int idx = beg + it * 4 + eo;
        float ex = 0.f;
        if (idx < end) {
            int s = g_csrc[idx];
            float e = g_el[s * 8 + h1] + er_a;
            e = (e > 0.f) ? e : 0.01f * e;
            ex = __expf(e);
        }
        denom += ex;
    }
    denom += __shfl_xor_sync(0xffffffffu, denom, 8);
    denom += __shfl_xor_sync(0xffffffffu, denom, 16);

    int h2 = lane >> 2;
    float dh = __shfl_sync(0xffffffffu, denom, h2);
    float er_b = __shfl_sync(0xffffffffu, er_a, h2);
    float rd = (dh > 0.f) ? (1.0f / dh) : 0.f;

    // pass 2: weighted aggregation (lane owns 4 contiguous dims in head h2)
    float4 acc = make_float4(0.f, 0.f, 0.f, 0.f);
    const float4* z4 = (const float4*)g_z;
    for (int i = beg; i < end; i++) {
        int s = g_csrc[i];
        float e = g_el[s * 8 + h2] + er_b;
        e = (e > 0.f) ? e : 0.01f * e;
        float alpha = __expf(e) * rd;
        float4 zv = z4[(size_t)s * 32 + lane];
        acc.x += alpha * zv.x;
        acc.y += alpha * zv.y;
        acc.z += alpha * zv.z;
        acc.w += alpha * zv.w;
    }

    // elu + residual
    float4 xr = ((const float4*)x)[(size_t)d * 32 + lane];
    acc.x = ((acc.x > 0.f) ? acc.x : (__expf(acc.x) - 1.f)) + xr.x;
    acc.y = ((acc.y > 0.f) ? acc.y : (__expf(acc.y) - 1.f)) + xr.y;
    acc.z = ((acc.z > 0.f) ? acc.z : (__expf(acc.z) - 1.f)) + xr.z;
    acc.w = ((acc.w > 0.f) ? acc.w : (__expf(acc.w) - 1.f)) + xr.w;
    ((float4*)g_h)[(size_t)d * 32 + lane] = acc;

    // fused LayerNorm
    float s = acc.x + acc.y + acc.z + acc.w;
#pragma unroll
    for (int o = 16; o; o >>= 1) s += __shfl_xor_sync(0xffffffffu, s, o);
    float mu = s * (1.f / 128.f);
    float dx = acc.x - mu, dy = acc.y - mu, dz = acc.z - mu, dw = acc.w - mu;
    float q = dx * dx + dy * dy + dz * dz + dw * dw;
#pragma unroll
    for (int o = 16; o; o >>= 1) q += __shfl_xor_sync(0xffffffffu, q, o);
    float rs = rsqrtf(q * (1.f / 128.f) + 1e-6f);
    float4 g4 = ((const float4*)gg)[lane];
    float4 b4 = ((const float4*)bb)[lane];
    float4 o4 = make_float4(dx * rs * g4.x + b4.x, dy * rs * g4.y + b4.y,
                            dz * rs * g4.z + b4.z, dw * rs * g4.w + b4.w);
    ((float4*)g_lnv)[(size_t)d * 32 + lane] = o4;
}

// =====================================================================
extern "C" void kernel_launch(void* const* d_in, const int* in_sizes, int n_in,
                              void* d_out, int out_size)
{
    const float* x    = (const float*)d_in[0];
    const float* fcw  = (const float*)d_in[1];
    const float* a_l  = (const float*)d_in[2];
    const float* a_r  = (const float*)d_in[3];
    const float* ln_g = (const float*)d_in[4];
    const float* ln_b = (const float*)d_in[5];
    const float* w1   = (const float*)d_in[6];
    const float* b1   = (const float*)d_in[7];
    const float* w2   = (const float*)d_in[8];
    const float* b2   = (const float*)d_in[9];
    const int*   src  = (const int*)d_in[10];
    const int*   dst  = (const int*)d_in[11];

    int n = in_sizes[0] / 128;
    int E = in_sizes[10];

    float* g_z_p;     cudaGetSymbolAddress((void**)&g_z_p, g_z);
    float* g_lnv_p;   cudaGetSymbolAddress((void**)&g_lnv_p, g_lnv);
    float* g_inter_p; cudaGetSymbolAddress((void**)&g_inter_p, g_inter);
    float* g_h_p;     cudaGetSymbolAddress((void**)&g_h_p, g_h);

    int mblk = (n + 127) / 128;

    // CSR build
    zero_cnt_kernel<<<(n + 255) / 256, 256>>>(n);
    hist_kernel<<<(E + 255) / 256, 256>>>(dst, E);
    scan_kernel<<<1, 1024>>>(n);
    scatter_kernel<<<(E + 255) / 256, 256>>>(src, dst, E);

    // projection + attention coefficients
    gemm_kernel<128, 0><<<dim3(mblk, 1), 256>>>(x, fcw, nullptr, nullptr, g_z_p, n);
    eler_kernel<<<(n + 7) / 8, 256>>>(a_l, a_r, n);

    // GAT aggregation + elu + residual + LN
    gat_ln_kernel<<<(n + 7) / 8, 256>>>(x, ln_g, ln_b, n);

    // FFN
    gemm_kernel<128, 1><<<dim3(mblk, 4), 256>>>(g_lnv_p, w1, b1, nullptr, g_inter_p, n);
    gemm_kernel<512, 2><<<dim3(mblk, 1), 256>>>(g_inter_p, w2, b2, g_h_p, (float*)d_out, n);
}

// round 8
// speedup vs baseline: 1.1602x; 1.1602x over previous
#include <cuda_runtime.h>
#include <cuda_bf16.h>
#include <stdint.h>
#include <math.h>

#define NMAX 50000
#define EMAX 800000

// ---------------- scratch (static __device__ — no allocation) ----------------
__device__ float g_z[(size_t)NMAX * 128];        // projections fp32 (gathered by GAT)
__device__ float g_el[(size_t)NMAX * 8];
__device__ float g_er[(size_t)NMAX * 8];
__device__ float g_h[(size_t)NMAX * 128];        // elu(gat)+x
__device__ __nv_bfloat16 g_xhi[(size_t)NMAX * 128];
__device__ __nv_bfloat16 g_xlo[(size_t)NMAX * 128];
__device__ __nv_bfloat16 g_lnvhi[(size_t)NMAX * 128];
__device__ __nv_bfloat16 g_lnvlo[(size_t)NMAX * 128];
__device__ __nv_bfloat16 g_inthi[(size_t)NMAX * 512];
__device__ __nv_bfloat16 g_intlo[(size_t)NMAX * 512];
__device__ __nv_bfloat16 g_fcwthi[128 * 128];    // B[n][k] = fc_w[h][k][o]
__device__ __nv_bfloat16 g_fcwtlo[128 * 128];
__device__ __nv_bfloat16 g_w1thi[512 * 128];     // B[n][k] = w1[k][n]
__device__ __nv_bfloat16 g_w1tlo[512 * 128];
__device__ __nv_bfloat16 g_w2thi[128 * 512];     // B[n][k] = w2[k][n]
__device__ __nv_bfloat16 g_w2tlo[128 * 512];
__device__ int g_cnt[NMAX];
__device__ int g_off[NMAX + 1];
__device__ int g_cur[NMAX];
__device__ int g_csrc[EMAX];

// ---------------- helpers ----------------
__device__ __forceinline__ uint32_t smem_to_u32(const void* p) {
    uint32_t a;
    asm("{ .reg .u64 t; cvta.to.shared.u64 t, %1; cvt.u32.u64 %0, t; }" : "=r"(a) : "l"(p));
    return a;
}
__device__ __forceinline__ void ldsm_x4(uint32_t& r0, uint32_t& r1, uint32_t& r2, uint32_t& r3,
                                        uint32_t addr) {
    asm volatile("ldmatrix.sync.aligned.m8n8.x4.shared.b16 {%0,%1,%2,%3}, [%4];"
                 : "=r"(r0), "=r"(r1), "=r"(r2), "=r"(r3) : "r"(addr));
}
__device__ __forceinline__ void mma16816(float* c, const uint32_t* a, const uint32_t* b) {
    asm volatile(
        "mma.sync.aligned.m16n8k16.row.col.f32.bf16.bf16.f32 "
        "{%0,%1,%2,%3}, {%4,%5,%6,%7}, {%8,%9}, {%0,%1,%2,%3};"
        : "+f"(c[0]), "+f"(c[1]), "+f"(c[2]), "+f"(c[3])
        : "r"(a[0]), "r"(a[1]), "r"(a[2]), "r"(a[3]), "r"(b[0]), "r"(b[1]));
}
__device__ __forceinline__ float gelu_exact(float v) {
    return 0.5f * v * (1.0f + erff(v * 0.70710678118654752440f));
}
__device__ __forceinline__ void bsplit(float v, __nv_bfloat16& h, __nv_bfloat16& l) {
    h = __float2bfloat16(v);
    l = __float2bfloat16(v - __bfloat162float(h));
}
__device__ __forceinline__ unsigned pack_bf2(__nv_bfloat16 a, __nv_bfloat16 b) {
    unsigned short ua = *(unsigned short*)&a, ub = *(unsigned short*)&b;
    return (unsigned)ua | ((unsigned)ub << 16);
}

// =====================================================================
// HMMA GEMM: C[M,N] = A[M,KTOT] @ B_t[N,KTOT]^T, split-bf16 3-term
// compensation (Ah·Bh + Ah·Bl + Al·Bh), fp32 register accumulation.
// CTA: 128x128 tile, 256 threads (8 warps, 2m x 4n), warp tile 64x32.
// BK=32. smem rows padded to 80B for conflict-free ldmatrix.
// EPI: 0 = fp32 out (proj); 1 = gelu(acc+bias) -> bf16 hi/lo (ffn1);
//      2 = acc+bias+res -> fp32 (ffn2)
// =====================================================================
#define SROW 40   // bf16 units per smem row (80 bytes)

template<int KTOT, int EPI>
__global__ __launch_bounds__(256) void mgemm_kernel(
    const __nv_bfloat16* __restrict__ Ahi, const __nv_bfloat16* __restrict__ Alo,
    const __nv_bfloat16* __restrict__ Bhi, const __nv_bfloat16* __restrict__ Blo,
    const float* __restrict__ bias, const float* __restrict__ res,
    float* __restrict__ outf, __nv_bfloat16* __restrict__ outhi,
    __nv_bfloat16* __restrict__ outlo, int M)
{
    __shared__ __align__(16) __nv_bfloat16 sAh[128 * SROW];
    __shared__ __align__(16) __nv_bfloat16 sAl[128 * SROW];
    __shared__ __align__(16) __nv_bfloat16 sBh[128 * SROW];
    __shared__ __align__(16) __nv_bfloat16 sBl[128 * SROW];

    const int tid = threadIdx.x;
    const int wid = tid >> 5, lane = tid & 31;
    const int wm = wid & 1, wn = wid >> 1;          // warp: rows wm*64, cols wn*32
    const int row0 = blockIdx.x * 128;
    const int col0 = blockIdx.y * 128;

    const uint32_t sAh_b = smem_to_u32(sAh);
    const uint32_t sAl_b = smem_to_u32(sAl);
    const uint32_t sBh_b = smem_to_u32(sBh);
    const uint32_t sBl_b = smem_to_u32(sBl);

    float acc[4][4][4];
#pragma unroll
    for (int i = 0; i < 4; i++)
#pragma unroll
        for (int j = 0; j < 4; j++)
#pragma unroll
            for (int p = 0; p < 4; p++) acc[i][j][p] = 0.f;

    const uint4* Ahi4 = (const uint4*)Ahi;
    const uint4* Alo4 = (const uint4*)Alo;
    const uint4* Bhi4 = (const uint4*)Bhi;
    const uint4* Blo4 = (const uint4*)Blo;
    constexpr int KU4 = KTOT / 8;

    // ldmatrix lane-address components
    const int lg = lane >> 3, lr = lane & 7;
    const int a_row_off = lr + ((lg & 1) ? 8 : 0);       // A: +8 rows for odd group
    const int a_k_off   = (lg >= 2) ? 8 : 0;             // A: +8 k for groups 2,3
    const int b_row_off = lr + ((lg >= 2) ? 8 : 0);      // B: +8 n for groups 2,3
    const int b_k_off   = (lg & 1) ? 8 : 0;              // B: +8 k for odd group

#pragma unroll 1
    for (int kc = 0; kc < KTOT / 32; kc++) {
        // ---- fill smem: 128 rows x 32 bf16 (4 uint4 per row) each ----
#pragma unroll
        for (int i = 0; i < 2; i++) {
            int idx = tid + i * 256;
            int r = idx >> 2, c8 = idx & 3;
            uint32_t sby = (uint32_t)(r * 80 + c8 * 16);
            int ga = row0 + r;
            uint4 vh = make_uint4(0u, 0u, 0u, 0u), vl = vh;
            if (ga < M) {
                vh = Ahi4[(size_t)ga * KU4 + kc * 4 + c8];
                vl = Alo4[(size_t)ga * KU4 + kc * 4 + c8];
            }
            *(uint4*)((char*)sAh + sby) = vh;
            *(uint4*)((char*)sAl + sby) = vl;
            int gb = col0 + r;
            *(uint4*)((char*)sBh + sby) = Bhi4[(size_t)gb * KU4 + kc * 4 + c8];
            *(uint4*)((char*)sBl + sby) = Blo4[(size_t)gb * KU4 + kc * 4 + c8];
        }
        __syncthreads();

#pragma unroll
        for (int k16 = 0; k16 < 2; k16++) {
            const int kb = k16 * 16;
            // B fragments: 4 n-tiles (8 regs hi, 8 regs lo)
            uint32_t bh[8], bl[8];
#pragma unroll
            for (int np = 0; np < 2; np++) {
                uint32_t ab = (uint32_t)((wn * 32 + np * 16 + b_row_off) * 80 +
                                         (kb + b_k_off) * 2);
                ldsm_x4(bh[np * 4 + 0], bh[np * 4 + 1], bh[np * 4 + 2], bh[np * 4 + 3],
                        sBh_b + ab);
                ldsm_x4(bl[np * 4 + 0], bl[np * 4 + 1], bl[np * 4 + 2], bl[np * 4 + 3],
                        sBl_b + ab);
            }
#pragma unroll
            for (int mt = 0; mt < 4; mt++) {
                uint32_t aa = (uint32_t)((wm * 64 + mt * 16 + a_row_off) * 80 +
                                         (kb + a_k_off) * 2);
                uint32_t ah[4], al[4];
                ldsm_x4(ah[0], ah[1], ah[2], ah[3], sAh_b + aa);
                ldsm_x4(al[0], al[1], al[2], al[3], sAl_b + aa);
#pragma unroll
                for (int nt = 0; nt < 4; nt++) {
                    mma16816(acc[mt][nt], ah, &bh[nt * 2]);   // hi*hi
                    mma16816(acc[mt][nt], ah, &bl[nt * 2]);   // hi*lo
                    mma16816(acc[mt][nt], al, &bh[nt * 2]);   // lo*hi
                }
            }
        }
        __syncthreads();
    }

    // ---- epilogue: C frag (gid, tg): c0,c1 @ (row, col..col+1); c2,c3 @ row+8 ----
    const int gid = lane >> 2, tg = lane & 3;
    constexpr int ONST = (EPI == 1) ? 512 : 128;
#pragma unroll
    for (int mt = 0; mt < 4; mt++) {
#pragma unroll
        for (int half = 0; half < 2; half++) {
            int grow = row0 + wm * 64 + mt * 16 + gid + half * 8;
            if (grow >= M) continue;
#pragma unroll
            for (int nt = 0; nt < 4; nt++) {
                int col = col0 + wn * 32 + nt * 8 + tg * 2;
                float vx = acc[mt][nt][half * 2 + 0];
                float vy = acc[mt][nt][half * 2 + 1];
                if (EPI == 0) {
                    *(float2*)&outf[(size_t)grow * 128 + col] = make_float2(vx, vy);
                } else if (EPI == 1) {
                    vx = gelu_exact(vx + bias[col]);
                    vy = gelu_exact(vy + bias[col + 1]);
                    __nv_bfloat16 bh0, bh1, bl0, bl1;
                    bsplit(vx, bh0, bl0);
                    bsplit(vy, bh1, bl1);
                    *(unsigned*)&outhi[(size_t)grow * ONST + col] = pack_bf2(bh0, bh1);
                    *(unsigned*)&outlo[(size_t)grow * ONST + col] = pack_bf2(bl0, bl1);
                } else {
                    const float2 rv = *(const float2*)&res[(size_t)grow * 128 + col];
                    vx += bias[col] + rv.x;
                    vy += bias[col + 1] + rv.y;
                    *(float2*)&outf[(size_t)grow * 128 + col] = make_float2(vx, vy);
                }
            }
        }
    }
}

// =====================================================================
// conversion kernels
// =====================================================================
__global__ void cvt_split_kernel(const float* __restrict__ in,
                                 __nv_bfloat16* __restrict__ hi,
                                 __nv_bfloat16* __restrict__ lo, int n4)
{
    int i = blockIdx.x * blockDim.x + threadIdx.x;
    if (i >= n4) return;
    float4 v = ((const float4*)in)[i];
    __nv_bfloat16 bh0, bh1, bh2, bh3, bl0, bl1, bl2, bl3;
    bsplit(v.x, bh0, bl0); bsplit(v.y, bh1, bl1);
    bsplit(v.z, bh2, bl2); bsplit(v.w, bh3, bl3);
    ((uint2*)hi)[i] = make_uint2(pack_bf2(bh0, bh1), pack_bf2(bh2, bh3));
    ((uint2*)lo)[i] = make_uint2(pack_bf2(bl0, bl1), pack_bf2(bl2, bl3));
}

// w [K][N] fp32 -> B[n][k] bf16 hi/lo
__global__ void cvt_wt_kernel(const float* __restrict__ w,
                              __nv_bfloat16* __restrict__ hi,
                              __nv_bfloat16* __restrict__ lo, int K, int N)
{
    int id = blockIdx.x * blockDim.x + threadIdx.x;
    if (id >= N * K) return;
    int n = id / K, k = id - n * K;
    float v = w[k * N + n];
    __nv_bfloat16 bh, bl;
    bsplit(v, bh, bl);
    hi[id] = bh; lo[id] = bl;
}

// fc_w [8][128][16] -> B[n][k], n = h*16+o
__global__ void cvt_fcw_kernel(const float* __restrict__ w,
                               __nv_bfloat16* __restrict__ hi,
                               __nv_bfloat16* __restrict__ lo)
{
    int id = blockIdx.x * blockDim.x + threadIdx.x;
    if (id >= 128 * 128) return;
    int n = id >> 7, k = id & 127;
    int h = n >> 4, o = n & 15;
    float v = w[h * 2048 + k * 16 + o];
    __nv_bfloat16 bh, bl;
    bsplit(v, bh, bl);
    hi[id] = bh; lo[id] = bl;
}

// =====================================================================
// el/er: warp per node
// =====================================================================
__global__ __launch_bounds__(256) void eler_kernel(
    const float* __restrict__ a_l, const float* __restrict__ a_r, int n)
{
    int warp = (blockIdx.x * blockDim.x + threadIdx.x) >> 5;
    int lane = threadIdx.x & 31;
    if (warp >= n) return;
    float4 z = ((const float4*)g_z)[(size_t)warp * 32 + lane];
    float4 al = ((const float4*)a_l)[lane];
    float4 ar = ((const float4*)a_r)[lane];
    float sl = z.x * al.x + z.y * al.y + z.z * al.z + z.w * al.w;
    float sr = z.x * ar.x + z.y * ar.y + z.z * ar.z + z.w * ar.w;
    sl += __shfl_xor_sync(0xffffffffu, sl, 1);
    sl += __shfl_xor_sync(0xffffffffu, sl, 2);
    sr += __shfl_xor_sync(0xffffffffu, sr, 1);
    sr += __shfl_xor_sync(0xffffffffu, sr, 2);
    if ((lane & 3) == 0) {
        int head = lane >> 2;
        g_el[warp * 8 + head] = sl;
        g_er[warp * 8 + head] = sr;
    }
}

// =====================================================================
// CSR build
// =====================================================================
__global__ void zero_cnt_kernel(int n) {
    int i = blockIdx.x * blockDim.x + threadIdx.x;
    if (i < n) g_cnt[i] = 0;
}
__global__ void hist_kernel(const int* __restrict__ dst, int E) {
    int i = blockIdx.x * blockDim.x + threadIdx.x;
    if (i < E) atomicAdd(&g_cnt[dst[i]], 1);
}
__global__ __launch_bounds__(1024) void scan_kernel(int n) {
    int t = threadIdx.x;
    int chunk = (n + 1023) >> 10;
    int b = t * chunk;
    int e = b + chunk; if (e > n) e = n;
    int s = 0;
    for (int i = b; i < e; i++) s += g_cnt[i];
    int own = s;
    int lane = t & 31, w = t >> 5;
#pragma unroll
    for (int d = 1; d < 32; d <<= 1) {
        int v = __shfl_up_sync(0xffffffffu, s, d);
        if (lane >= d) s += v;
    }
    __shared__ int ws[32];
    if (lane == 31) ws[w] = s;
    __syncthreads();
    if (w == 0) {
        int v = ws[lane];
#pragma unroll
        for (int d = 1; d < 32; d <<= 1) {
            int u = __shfl_up_sync(0xffffffffu, v, d);
            if (lane >= d) v += u;
        }
        ws[lane] = v;
    }
    __syncthreads();
    int run = s - own + (w ? ws[w - 1] : 0);
    for (int i = b; i < e; i++) {
        g_off[i] = run;
        g_cur[i] = run;
        run += g_cnt[i];
    }
    if (t == 1023) g_off[n] = ws[31];
}
__global__ void scatter_kernel(const int* __restrict__ src, const int* __restrict__ dst, int E) {
    int i = blockIdx.x * blockDim.x + threadIdx.x;
    if (i < E) {
        int d = dst[i];
        int p = atomicAdd(&g_cur[d], 1);
        g_csrc[p] = src[i];
    }
}

// =====================================================================
// GAT: softmax + aggregation + elu + residual + fused LN (bf16-split out)
// =====================================================================
__global__ __launch_bounds__(256) void gat_ln_kernel(
    const float* __restrict__ x,
    const float* __restrict__ gg, const float* __restrict__ bb, int n)
{
    int warp = (blockIdx.x * blockDim.x + threadIdx.x) >> 5;
    int lane = threadIdx.x & 31;
    if (warp >= n) return;
    int d = warp;
    int beg = g_off[d], end = g_off[d + 1];

    int h1 = lane & 7, eo = lane >> 3;
    float er_a = g_er[d * 8 + h1];

    float denom = 0.f;
    int iters = (end - beg + 3) >> 2;
    for (int it = 0; it < iters; it++) {
        int idx = beg + it * 4 + eo;
        float ex = 0.f;
        if (idx < end) {
            int s = g_csrc[idx];
            float e = g_el[s * 8 + h1] + er_a;
            e = (e > 0.f) ? e : 0.01f * e;
            ex = __expf(e);
        }
        denom += ex;
    }
    denom += __shfl_xor_sync(0xffffffffu, denom, 8);
    denom += __shfl_xor_sync(0xffffffffu, denom, 16);

    int h2 = lane >> 2;
    float dh = __shfl_sync(0xffffffffu, denom, h2);
    float er_b = __shfl_sync(0xffffffffu, er_a, h2);
    float rd = (dh > 0.f) ? (1.0f / dh) : 0.f;

    float4 acc = make_float4(0.f, 0.f, 0.f, 0.f);
    const float4* z4 = (const float4*)g_z;
    for (int i = beg; i < end; i++) {
        int s = g_csrc[i];
        float e = g_el[s * 8 + h2] + er_b;
        e = (e > 0.f) ? e : 0.01f * e;
        float alpha = __expf(e) * rd;
        float4 zv = z4[(size_t)s * 32 + lane];
        acc.x += alpha * zv.x;
        acc.y += alpha * zv.y;
        acc.z += alpha * zv.z;
        acc.w += alpha * zv.w;
    }

    float4 xr = ((const float4*)x)[(size_t)d * 32 + lane];
    acc.x = ((acc.x > 0.f) ? acc.x : (__expf(acc.x) - 1.f)) + xr.x;
    acc.y = ((acc.y > 0.f) ? acc.y : (__expf(acc.y) - 1.f)) + xr.y;
    acc.z = ((acc.z > 0.f) ? acc.z : (__expf(acc.z) - 1.f)) + xr.z;
    acc.w = ((acc.w > 0.f) ? acc.w : (__expf(acc.w) - 1.f)) + xr.w;
    ((float4*)g_h)[(size_t)d * 32 + lane] = acc;

    float s = acc.x + acc.y + acc.z + acc.w;
#pragma unroll
    for (int o = 16; o; o >>= 1) s += __shfl_xor_sync(0xffffffffu, s, o);
    float mu = s * (1.f / 128.f);
    float dx = acc.x - mu, dy = acc.y - mu, dz = acc.z - mu, dw = acc.w - mu;
    float q = dx * dx + dy * dy + dz * dz + dw * dw;
#pragma unroll
    for (int o = 16; o; o >>= 1) q += __shfl_xor_sync(0xffffffffu, q, o);
    float rs = rsqrtf(q * (1.f / 128.f) + 1e-6f);
    float4 g4 = ((const float4*)gg)[lane];
    float4 b4 = ((const float4*)bb)[lane];
    float4 o4 = make_float4(dx * rs * g4.x + b4.x, dy * rs * g4.y + b4.y,
                            dz * rs * g4.z + b4.z, dw * rs * g4.w + b4.w);
    __nv_bfloat16 bh0, bh1, bh2, bh3, bl0, bl1, bl2, bl3;
    bsplit(o4.x, bh0, bl0); bsplit(o4.y, bh1, bl1);
    bsplit(o4.z, bh2, bl2); bsplit(o4.w, bh3, bl3);
    ((uint2*)g_lnvhi)[(size_t)d * 32 + lane] = make_uint2(pack_bf2(bh0, bh1), pack_bf2(bh2, bh3));
    ((uint2*)g_lnvlo)[(size_t)d * 32 + lane] = make_uint2(pack_bf2(bl0, bl1), pack_bf2(bl2, bl3));
}

// =====================================================================
extern "C" void kernel_launch(void* const* d_in, const int* in_sizes, int n_in,
                              void* d_out, int out_size)
{
    const float* x    = (const float*)d_in[0];
    const float* fcw  = (const float*)d_in[1];
    const float* a_l  = (const float*)d_in[2];
    const float* a_r  = (const float*)d_in[3];
    const float* ln_g = (const float*)d_in[4];
    const float* ln_b = (const float*)d_in[5];
    const float* w1   = (const float*)d_in[6];
    const float* b1   = (const float*)d_in[7];
    const float* w2   = (const float*)d_in[8];
    const float* b2   = (const float*)d_in[9];
    const int*   src  = (const int*)d_in[10];
    const int*   dst  = (const int*)d_in[11];

    int n = in_sizes[0] / 128;
    int E = in_sizes[10];

    float *g_z_p, *g_h_p;
    __nv_bfloat16 *xhi, *xlo, *lnvhi, *lnvlo, *inthi, *intlo;
    __nv_bfloat16 *fcwhi, *fcwlo, *w1hi, *w1lo, *w2hi, *w2lo;
    cudaGetSymbolAddress((void**)&g_z_p, g_z);
    cudaGetSymbolAddress((void**)&g_h_p, g_h);
    cudaGetSymbolAddress((void**)&xhi, g_xhi);
    cudaGetSymbolAddress((void**)&xlo, g_xlo);
    cudaGetSymbolAddress((void**)&lnvhi, g_lnvhi);
    cudaGetSymbolAddress((void**)&lnvlo, g_lnvlo);
    cudaGetSymbolAddress((void**)&inthi, g_inthi);
    cudaGetSymbolAddress((void**)&intlo, g_intlo);
    cudaGetSymbolAddress((void**)&fcwhi, g_fcwthi);
    cudaGetSymbolAddress((void**)&fcwlo, g_fcwtlo);
    cudaGetSymbolAddress((void**)&w1hi, g_w1thi);
    cudaGetSymbolAddress((void**)&w1lo, g_w1tlo);
    cudaGetSymbolAddress((void**)&w2hi, g_w2thi);
    cudaGetSymbolAddress((void**)&w2lo, g_w2tlo);

    int mblk = (n + 127) / 128;

    // conversions
    cvt_split_kernel<<<(n * 32 + 255) / 256, 256>>>(x, xhi, xlo, n * 32);
    cvt_fcw_kernel<<<(128 * 128 + 255) / 256, 256>>>(fcw, fcwhi, fcwlo);
    cvt_wt_kernel<<<(512 * 128 + 255) / 256, 256>>>(w1, w1hi, w1lo, 128, 512);
    cvt_wt_kernel<<<(512 * 128 + 255) / 256, 256>>>(w2, w2hi, w2lo, 512, 128);

    // CSR build
    zero_cnt_kernel<<<(n + 255) / 256, 256>>>(n);
    hist_kernel<<<(E + 255) / 256, 256>>>(dst, E);
    scan_kernel<<<1, 1024>>>(n);
    scatter_kernel<<<(E + 255) / 256, 256>>>(src, dst, E);

    // projection (tensor cores) + attention coefficients
    mgemm_kernel<128, 0><<<dim3(mblk, 1), 256>>>(
        xhi, xlo, fcwhi, fcwlo, nullptr, nullptr, g_z_p, nullptr, nullptr, n);
    eler_kernel<<<(n + 7) / 8, 256>>>(a_l, a_r, n);

    // GAT aggregation + elu + residual + LN (emits lnv bf16 hi/lo)
    gat_ln_kernel<<<(n + 7) / 8, 256>>>(x, ln_g, ln_b, n);

    // FFN (tensor cores)
    mgemm_kernel<128, 1><<<dim3(mblk, 4), 256>>>(
        lnvhi, lnvlo, w1hi, w1lo, b1, nullptr, nullptr, inthi, intlo, n);
    mgemm_kernel<512, 2><<<dim3(mblk, 1), 256>>>(
        inthi, intlo, w2hi, w2lo, b2, g_h_p, (float*)d_out, nullptr, nullptr, n);
}

// round 9
// speedup vs baseline: 1.4320x; 1.2342x over previous
#include <cuda_runtime.h>
#include <cuda_bf16.h>
#include <stdint.h>
#include <math.h>

#define NMAX 50000
#define EMAX 800000

// ---------------- scratch (static __device__ — no allocation) ----------------
__device__ float g_z[(size_t)NMAX * 128];        // projections fp32 (gathered by GAT)
__device__ float g_el[(size_t)NMAX * 8];
__device__ float g_er[(size_t)NMAX * 8];
__device__ float g_h[(size_t)NMAX * 128];        // elu(gat)+x
__device__ __nv_bfloat16 g_xhi[(size_t)NMAX * 128];
__device__ __nv_bfloat16 g_xlo[(size_t)NMAX * 128];
__device__ __nv_bfloat16 g_lnvhi[(size_t)NMAX * 128];
__device__ __nv_bfloat16 g_lnvlo[(size_t)NMAX * 128];
__device__ __nv_bfloat16 g_inthi[(size_t)NMAX * 512];
__device__ __nv_bfloat16 g_intlo[(size_t)NMAX * 512];
__device__ __nv_bfloat16 g_fcwthi[128 * 128];    // B[n][k] = fc_w[h][k][o]
__device__ __nv_bfloat16 g_fcwtlo[128 * 128];
__device__ __nv_bfloat16 g_w1thi[512 * 128];     // B[n][k] = w1[k][n]
__device__ __nv_bfloat16 g_w1tlo[512 * 128];
__device__ __nv_bfloat16 g_w2thi[128 * 512];     // B[n][k] = w2[k][n]
__device__ __nv_bfloat16 g_w2tlo[128 * 512];
__device__ int g_cnt[NMAX];
__device__ int g_off[NMAX + 1];
__device__ int g_cur[NMAX];
__device__ int g_csrc[EMAX];

// ---------------- helpers ----------------
__device__ __forceinline__ uint32_t smem_to_u32(const void* p) {
    uint32_t a;
    asm("{ .reg .u64 t; cvta.to.shared.u64 t, %1; cvt.u32.u64 %0, t; }" : "=r"(a) : "l"(p));
    return a;
}
__device__ __forceinline__ void ldsm_x4(uint32_t& r0, uint32_t& r1, uint32_t& r2, uint32_t& r3,
                                        uint32_t addr) {
    asm volatile("ldmatrix.sync.aligned.m8n8.x4.shared.b16 {%0,%1,%2,%3}, [%4];"
                 : "=r"(r0), "=r"(r1), "=r"(r2), "=r"(r3) : "r"(addr));
}
__device__ __forceinline__ void mma16816(float* c, const uint32_t* a, const uint32_t* b) {
    asm volatile(
        "mma.sync.aligned.m16n8k16.row.col.f32.bf16.bf16.f32 "
        "{%0,%1,%2,%3}, {%4,%5,%6,%7}, {%8,%9}, {%0,%1,%2,%3};"
        : "+f"(c[0]), "+f"(c[1]), "+f"(c[2]), "+f"(c[3])
        : "r"(a[0]), "r"(a[1]), "r"(a[2]), "r"(a[3]), "r"(b[0]), "r"(b[1]));
}
__device__ __forceinline__ void cpa16(uint32_t d, const void* s) {
    asm volatile("cp.async.cg.shared.global [%0], [%1], 16;" :: "r"(d), "l"(s));
}
__device__ __forceinline__ float gelu_exact(float v) {
    return 0.5f * v * (1.0f + erff(v * 0.70710678118654752440f));
}
__device__ __forceinline__ void bsplit(float v, __nv_bfloat16& h, __nv_bfloat16& l) {
    h = __float2bfloat16(v);
    l = __float2bfloat16(v - __bfloat162float(h));
}
__device__ __forceinline__ unsigned pack_bf2(__nv_bfloat16 a, __nv_bfloat16 b) {
    unsigned short ua = *(unsigned short*)&a, ub = *(unsigned short*)&b;
    return (unsigned)ua | ((unsigned)ub << 16);
}

// =====================================================================
// HMMA GEMM, cp.async double-buffered.
// C[M,N] = A[M,KTOT] @ B_t[N,KTOT]^T, split-bf16 3-term compensation.
// CTA: 128x128 tile, 256 threads (8 warps, 2m x 4n), warp tile 64x32.
// BK=32. smem rows padded to 80B for conflict-free ldmatrix.
// Dynamic smem: 2 stages x 4 arrays x 10240B = 81920B.
// EPI: 0 = fp32 out (proj); 1 = gelu(acc+bias) -> bf16 hi/lo (ffn1);
//      2 = acc+bias+res -> fp32 (ffn2)
// =====================================================================
#define TILE_B 10240        // one array (128 rows x 80B)
#define STAGE_B (4 * TILE_B)

template<int KTOT, int EPI>
__global__ __launch_bounds__(256) void mgemm_kernel(
    const __nv_bfloat16* __restrict__ Ahi, const __nv_bfloat16* __restrict__ Alo,
    const __nv_bfloat16* __restrict__ Bhi, const __nv_bfloat16* __restrict__ Blo,
    const float* __restrict__ bias, const float* __restrict__ res,
    float* __restrict__ outf, __nv_bfloat16* __restrict__ outhi,
    __nv_bfloat16* __restrict__ outlo, int M)
{
    extern __shared__ char smem[];
    const uint32_t sb = smem_to_u32(smem);

    const int tid = threadIdx.x;
    const int wid = tid >> 5, lane = tid & 31;
    const int wm = wid & 1, wn = wid >> 1;          // warp: rows wm*64, cols wn*32
    const int row0 = blockIdx.x * 128;
    const int col0 = blockIdx.y * 128;

    float acc[4][4][4];
#pragma unroll
    for (int i = 0; i < 4; i++)
#pragma unroll
        for (int j = 0; j < 4; j++)
#pragma unroll
            for (int p = 0; p < 4; p++) acc[i][j][p] = 0.f;

    const uint4* Ahi4 = (const uint4*)Ahi;
    const uint4* Alo4 = (const uint4*)Alo;
    const uint4* Bhi4 = (const uint4*)Bhi;
    const uint4* Blo4 = (const uint4*)Blo;
    constexpr int KU4 = KTOT / 8;
    constexpr int NK = KTOT / 32;

    // per-thread fill coordinates (2 chunks of 16B per array per stage)
    const int fr0 = tid >> 2, fc0 = tid & 3;              // rows 0..63
    const int fr1 = fr0 + 64;                             // rows 64..127
    const uint32_t sby0 = (uint32_t)(fr0 * 80 + fc0 * 16);
    const uint32_t sby1 = (uint32_t)(fr1 * 80 + fc0 * 16);
    int ga0 = row0 + fr0; if (ga0 > M - 1) ga0 = M - 1;
    int ga1 = row0 + fr1; if (ga1 > M - 1) ga1 = M - 1;
    const int gb0 = col0 + fr0, gb1 = col0 + fr1;

    // ldmatrix lane-address components
    const int lg = lane >> 3, lr = lane & 7;
    const int a_row_off = lr + ((lg & 1) ? 8 : 0);
    const int a_k_off   = (lg >= 2) ? 8 : 0;
    const int b_row_off = lr + ((lg >= 2) ? 8 : 0);
    const int b_k_off   = (lg & 1) ? 8 : 0;

    auto load_stage = [&](int kc, int s) {
        const uint32_t st = sb + (uint32_t)s * STAGE_B;
        const int koff = kc * 4 + fc0;
        cpa16(st + sby0,                &Ahi4[(size_t)ga0 * KU4 + koff]);
        cpa16(st + sby1,                &Ahi4[(size_t)ga1 * KU4 + koff]);
        cpa16(st + TILE_B + sby0,       &Alo4[(size_t)ga0 * KU4 + koff]);
        cpa16(st + TILE_B + sby1,       &Alo4[(size_t)ga1 * KU4 + koff]);
        cpa16(st + 2 * TILE_B + sby0,   &Bhi4[(size_t)gb0 * KU4 + koff]);
        cpa16(st + 2 * TILE_B + sby1,   &Bhi4[(size_t)gb1 * KU4 + koff]);
        cpa16(st + 3 * TILE_B + sby0,   &Blo4[(size_t)gb0 * KU4 + koff]);
        cpa16(st + 3 * TILE_B + sby1,   &Blo4[(size_t)gb1 * KU4 + koff]);
        asm volatile("cp.async.commit_group;" ::: "memory");
    };

    load_stage(0, 0);

#pragma unroll 1
    for (int kc = 0; kc < NK; kc++) {
        if (kc + 1 < NK) {
            load_stage(kc + 1, (kc + 1) & 1);
            asm volatile("cp.async.wait_group 1;" ::: "memory");
        } else {
            asm volatile("cp.async.wait_group 0;" ::: "memory");
        }
        __syncthreads();

        const uint32_t st = sb + (uint32_t)(kc & 1) * STAGE_B;
        const uint32_t sAh_b = st, sAl_b = st + TILE_B;
        const uint32_t sBh_b = st + 2 * TILE_B, sBl_b = st + 3 * TILE_B;

#pragma unroll
        for (int k16 = 0; k16 < 2; k16++) {
            const int kb = k16 * 16;
            uint32_t bh[8], bl[8];
#pragma unroll
            for (int np = 0; np < 2; np++) {
                uint32_t ab = (uint32_t)((wn * 32 + np * 16 + b_row_off) * 80 +
                                         (kb + b_k_off) * 2);
                ldsm_x4(bh[np * 4 + 0], bh[np * 4 + 1], bh[np * 4 + 2], bh[np * 4 + 3],
                        sBh_b + ab);
                ldsm_x4(bl[np * 4 + 0], bl[np * 4 + 1], bl[np * 4 + 2], bl[np * 4 + 3],
                        sBl_b + ab);
            }
#pragma unroll
            for (int mt = 0; mt < 4; mt++) {
                uint32_t aa = (uint32_t)((wm * 64 + mt * 16 + a_row_off) * 80 +
                                         (kb + a_k_off) * 2);
                uint32_t ah[4], al[4];
                ldsm_x4(ah[0], ah[1], ah[2], ah[3], sAh_b + aa);
                ldsm_x4(al[0], al[1], al[2], al[3], sAl_b + aa);
#pragma unroll
                for (int nt = 0; nt < 4; nt++) {
                    mma16816(acc[mt][nt], ah, &bh[nt * 2]);   // hi*hi
                    mma16816(acc[mt][nt], ah, &bl[nt * 2]);   // hi*lo
                    mma16816(acc[mt][nt], al, &bh[nt * 2]);   // lo*hi
                }
            }
        }
        __syncthreads();
    }

    // ---- epilogue ----
    const int gid = lane >> 2, tg = lane & 3;
    constexpr int ONST = (EPI == 1) ? 512 : 128;
#pragma unroll
    for (int mt = 0; mt < 4; mt++) {
#pragma unroll
        for (int half = 0; half < 2; half++) {
            int grow = row0 + wm * 64 + mt * 16 + gid + half * 8;
            if (grow >= M) continue;
#pragma unroll
            for (int nt = 0; nt < 4; nt++) {
                int col = col0 + wn * 32 + nt * 8 + tg * 2;
                float vx = acc[mt][nt][half * 2 + 0];
                float vy = acc[mt][nt][half * 2 + 1];
                if (EPI == 0) {
                    *(float2*)&outf[(size_t)grow * 128 + col] = make_float2(vx, vy);
                } else if (EPI == 1) {
                    vx = gelu_exact(vx + bias[col]);
                    vy = gelu_exact(vy + bias[col + 1]);
                    __nv_bfloat16 bh0, bh1, bl0, bl1;
                    bsplit(vx, bh0, bl0);
                    bsplit(vy, bh1, bl1);
                    *(unsigned*)&outhi[(size_t)grow * ONST + col] = pack_bf2(bh0, bh1);
                    *(unsigned*)&outlo[(size_t)grow * ONST + col] = pack_bf2(bl0, bl1);
                } else {
                    const float2 rv = *(const float2*)&res[(size_t)grow * 128 + col];
                    vx += bias[col] + rv.x;
                    vy += bias[col + 1] + rv.y;
                    *(float2*)&outf[(size_t)grow * 128 + col] = make_float2(vx, vy);
                }
            }
        }
    }
}

// =====================================================================
// prep: fused conversions + g_cnt zeroing (segmented by global id)
//   seg0: x -> xhi/xlo (n*32 float4 groups)
//   seg1: fc_w -> fcwt hi/lo (16384)
//   seg2: w1 -> w1t hi/lo (65536)
//   seg3: w2 -> w2t hi/lo (65536)
//   seg4: g_cnt = 0 (n)
// =====================================================================
__global__ void prep_kernel(const float* __restrict__ x,
                            const float* __restrict__ fcw,
                            const float* __restrict__ w1,
                            const float* __restrict__ w2, int n)
{
    int id = blockIdx.x * blockDim.x + threadIdx.x;
    int nx = n * 32;
    if (id < nx) {
        float4 v = ((const float4*)x)[id];
        __nv_bfloat16 bh0, bh1, bh2, bh3, bl0, bl1, bl2, bl3;
        bsplit(v.x, bh0, bl0); bsplit(v.y, bh1, bl1);
        bsplit(v.z, bh2, bl2); bsplit(v.w, bh3, bl3);
        ((uint2*)g_xhi)[id] = make_uint2(pack_bf2(bh0, bh1), pack_bf2(bh2, bh3));
        ((uint2*)g_xlo)[id] = make_uint2(pack_bf2(bl0, bl1), pack_bf2(bl2, bl3));
        return;
    }
    id -= nx;
    if (id < 128 * 128) {
        int nn = id >> 7, k = id & 127;
        int h = nn >> 4, o = nn & 15;
        float v = fcw[h * 2048 + k * 16 + o];
        __nv_bfloat16 bh, bl;
        bsplit(v, bh, bl);
        g_fcwthi[id] = bh; g_fcwtlo[id] = bl;
        return;
    }
    id -= 128 * 128;
    if (id < 512 * 128) {
        int nn = id >> 7, k = id & 127;       // B[n][k] = w1[k][n], K=128, N=512
        float v = w1[k * 512 + nn];
        __nv_bfloat16 bh, bl;
        bsplit(v, bh, bl);
        g_w1thi[id] = bh; g_w1tlo[id] = bl;
        return;
    }
    id -= 512 * 128;
    if (id < 128 * 512) {
        int nn = id >> 9, k = id & 511;       // B[n][k] = w2[k][n], K=512, N=128
        float v = w2[k * 128 + nn];
        __nv_bfloat16 bh, bl;
        bsplit(v, bh, bl);
        g_w2thi[id] = bh; g_w2tlo[id] = bl;
        return;
    }
    id -= 128 * 512;
    if (id < n) g_cnt[id] = 0;
}

// =====================================================================
// el/er: warp per node
// =====================================================================
__global__ __launch_bounds__(256) void eler_kernel(
    const float* __restrict__ a_l, const float* __restrict__ a_r, int n)
{
    int warp = (blockIdx.x * blockDim.x + threadIdx.x) >> 5;
    int lane = threadIdx.x & 31;
    if (warp >= n) return;
    float4 z = ((const float4*)g_z)[(size_t)warp * 32 + lane];
    float4 al = ((const float4*)a_l)[lane];
    float4 ar = ((const float4*)a_r)[lane];
    float sl = z.x * al.x + z.y * al.y + z.z * al.z + z.w * al.w;
    float sr = z.x * ar.x + z.y * ar.y + z.z * ar.z + z.w * ar.w;
    sl += __shfl_xor_sync(0xffffffffu, sl, 1);
    sl += __shfl_xor_sync(0xffffffffu, sl, 2);
    sr += __shfl_xor_sync(0xffffffffu, sr, 1);
    sr += __shfl_xor_sync(0xffffffffu, sr, 2);
    if ((lane & 3) == 0) {
        int head = lane >> 2;
        g_el[warp * 8 + head] = sl;
        g_er[warp * 8 + head] = sr;
    }
}

// =====================================================================
// CSR build
// =====================================================================
__global__ void hist_kernel(const int* __restrict__ dst, int E) {
    int i = blockIdx.x * blockDim.x + threadIdx.x;
    if (i < E) atomicAdd(&g_cnt[dst[i]], 1);
}
__global__ __launch_bounds__(1024) void scan_kernel(int n) {
    int t = threadIdx.x;
    int chunk = (n + 1023) >> 10;
    int b = t * chunk;
    int e = b + chunk; if (e > n) e = n;
    int s = 0;
    for (int i = b; i < e; i++) s += g_cnt[i];
    int own = s;
    int lane = t & 31, w = t >> 5;
#pragma unroll
    for (int d = 1; d < 32; d <<= 1) {
        int v = __shfl_up_sync(0xffffffffu, s, d);
        if (lane >= d) s += v;
    }
    __shared__ int ws[32];
    if (lane == 31) ws[w] = s;
    __syncthreads();
    if (w == 0) {
        int v = ws[lane];
#pragma unroll
        for (int d = 1; d < 32; d <<= 1) {
            int u = __shfl_up_sync(0xffffffffu, v, d);
            if (lane >= d) v += u;
        }
        ws[lane] = v;
    }
    __syncthreads();
    int run = s - own + (w ? ws[w - 1] : 0);
    for (int i = b; i < e; i++) {
        g_off[i] = run;
        g_cur[i] = run;
        run += g_cnt[i];
    }
    if (t == 1023) g_off[n] = ws[31];
}
__global__ void scatter_kernel(const int* __restrict__ src, const int* __restrict__ dst, int E) {
    int i = blockIdx.x * blockDim.x + threadIdx.x;
    if (i < E) {
        int d = dst[i];
        int p = atomicAdd(&g_cur[d], 1);
        g_csrc[p] = src[i];
    }
}

// =====================================================================
// GAT: softmax + aggregation + elu + residual + fused LN (bf16-split out)
// =====================================================================
__global__ __launch_bounds__(256) void gat_ln_kernel(
    const float* __restrict__ x,
    const float* __restrict__ gg, const float* __restrict__ bb, int n)
{
    int warp = (blockIdx.x * blockDim.x + threadIdx.x) >> 5;
    int lane = threadIdx.x & 31;
    if (warp >= n) return;
    int d = warp;
    int beg = g_off[d], end = g_off[d + 1];

    int h1 = lane & 7, eo = lane >> 3;
    float er_a = g_er[d * 8 + h1];

    float denom = 0.f;
    int iters = (end - beg + 3) >> 2;
    for (int it = 0; it < iters; it++) {
        int idx = beg + it * 4 + eo;
        float ex = 0.f;
        if (idx < end) {
            int s = g_csrc[idx];
            float e = g_el[s * 8 + h1] + er_a;
            e = (e > 0.f) ? e : 0.01f * e;
            ex = __expf(e);
        }
        denom += ex;
    }
    denom += __shfl_xor_sync(0xffffffffu, denom, 8);
    denom += __shfl_xor_sync(0xffffffffu, denom, 16);

    int h2 = lane >> 2;
    float dh = __shfl_sync(0xffffffffu, denom, h2);
    float er_b = __shfl_sync(0xffffffffu, er_a, h2);
    float rd = (dh > 0.f) ? (1.0f / dh) : 0.f;

    float4 acc = make_float4(0.f, 0.f, 0.f, 0.f);
    const float4* z4 = (const float4*)g_z;
    for (int i = beg; i < end; i++) {
        int s = g_csrc[i];
        float e = g_el[s * 8 + h2] + er_b;
        e = (e > 0.f) ? e : 0.01f * e;
        float alpha = __expf(e) * rd;
        float4 zv = z4[(size_t)s * 32 + lane];
        acc.x += alpha * zv.x;
        acc.y += alpha * zv.y;
        acc.z += alpha * zv.z;
        acc.w += alpha * zv.w;
    }

    float4 xr = ((const float4*)x)[(size_t)d * 32 + lane];
    acc.x = ((acc.x > 0.f) ? acc.x : (__expf(acc.x) - 1.f)) + xr.x;
    acc.y = ((acc.y > 0.f) ? acc.y : (__expf(acc.y) - 1.f)) + xr.y;
    acc.z = ((acc.z > 0.f) ? acc.z : (__expf(acc.z) - 1.f)) + xr.z;
    acc.w = ((acc.w > 0.f) ? acc.w : (__expf(acc.w) - 1.f)) + xr.w;
    ((float4*)g_h)[(size_t)d * 32 + lane] = acc;

    float s = acc.x + acc.y + acc.z + acc.w;
#pragma unroll
    for (int o = 16; o; o >>= 1) s += __shfl_xor_sync(0xffffffffu, s, o);
    float mu = s * (1.f / 128.f);
    float dx = acc.x - mu, dy = acc.y - mu, dz = acc.z - mu, dw = acc.w - mu;
    float q = dx * dx + dy * dy + dz * dz + dw * dw;
#pragma unroll
    for (int o = 16; o; o >>= 1) q += __shfl_xor_sync(0xffffffffu, q, o);
    float rs = rsqrtf(q * (1.f / 128.f) + 1e-6f);
    float4 g4 = ((const float4*)gg)[lane];
    float4 b4 = ((const float4*)bb)[lane];
    float4 o4 = make_float4(dx * rs * g4.x + b4.x, dy * rs * g4.y + b4.y,
                            dz * rs * g4.z + b4.z, dw * rs * g4.w + b4.w);
    __nv_bfloat16 bh0, bh1, bh2, bh3, bl0, bl1, bl2, bl3;
    bsplit(o4.x, bh0, bl0); bsplit(o4.y, bh1, bl1);
    bsplit(o4.z, bh2, bl2); bsplit(o4.w, bh3, bl3);
    ((uint2*)g_lnvhi)[(size_t)d * 32 + lane] = make_uint2(pack_bf2(bh0, bh1), pack_bf2(bh2, bh3));
    ((uint2*)g_lnvlo)[(size_t)d * 32 + lane] = make_uint2(pack_bf2(bl0, bl1), pack_bf2(bl2, bl3));
}

// =====================================================================
extern "C" void kernel_launch(void* const* d_in, const int* in_sizes, int n_in,
                              void* d_out, int out_size)
{
    const float* x    = (const float*)d_in[0];
    const float* fcw  = (const float*)d_in[1];
    const float* a_l  = (const float*)d_in[2];
    const float* a_r  = (const float*)d_in[3];
    const float* ln_g = (const float*)d_in[4];
    const float* ln_b = (const float*)d_in[5];
    const float* w1   = (const float*)d_in[6];
    const float* b1   = (const float*)d_in[7];
    const float* w2   = (const float*)d_in[8];
    const float* b2   = (const float*)d_in[9];
    const int*   src  = (const int*)d_in[10];
    const int*   dst  = (const int*)d_in[11];

    int n = in_sizes[0] / 128;
    int E = in_sizes[10];

    float *g_z_p, *g_h_p;
    __nv_bfloat16 *xhi, *xlo, *lnvhi, *lnvlo, *inthi, *intlo;
    __nv_bfloat16 *fcwhi, *fcwlo, *w1hi, *w1lo, *w2hi, *w2lo;
    cudaGetSymbolAddress((void**)&g_z_p, g_z);
    cudaGetSymbolAddress((void**)&g_h_p, g_h);
    cudaGetSymbolAddress((void**)&xhi, g_xhi);
    cudaGetSymbolAddress((void**)&xlo, g_xlo);
    cudaGetSymbolAddress((void**)&lnvhi, g_lnvhi);
    cudaGetSymbolAddress((void**)&lnvlo, g_lnvlo);
    cudaGetSymbolAddress((void**)&inthi, g_inthi);
    cudaGetSymbolAddress((void**)&intlo, g_intlo);
    cudaGetSymbolAddress((void**)&fcwhi, g_fcwthi);
    cudaGetSymbolAddress((void**)&fcwlo, g_fcwtlo);
    cudaGetSymbolAddress((void**)&w1hi, g_w1thi);
    cudaGetSymbolAddress((void**)&w1lo, g_w1tlo);
    cudaGetSymbolAddress((void**)&w2hi, g_w2thi);
    cudaGetSymbolAddress((void**)&w2lo, g_w2tlo);

    const int SMEM_SZ = 2 * STAGE_B;   // 81920
    cudaFuncSetAttribute(mgemm_kernel<128, 0>, cudaFuncAttributeMaxDynamicSharedMemorySize, SMEM_SZ);
    cudaFuncSetAttribute(mgemm_kernel<128, 1>, cudaFuncAttributeMaxDynamicSharedMemorySize, SMEM_SZ);
    cudaFuncSetAttribute(mgemm_kernel<512, 2>, cudaFuncAttributeMaxDynamicSharedMemorySize, SMEM_SZ);

    int mblk = (n + 127) / 128;

    // fused conversions + cnt zeroing
    int prep_items = n * 32 + 128 * 128 + 512 * 128 + 128 * 512 + n;
    prep_kernel<<<(prep_items + 255) / 256, 256>>>(x, fcw, w1, w2, n);

    // CSR build
    hist_kernel<<<(E + 255) / 256, 256>>>(dst, E);
    scan_kernel<<<1, 1024>>>(n);
    scatter_kernel<<<(E + 255) / 256, 256>>>(src, dst, E);

    // projection (HMMA) + attention coefficients
    mgemm_kernel<128, 0><<<dim3(mblk, 1), 256, SMEM_SZ>>>(
        xhi, xlo, fcwhi, fcwlo, nullptr, nullptr, g_z_p, nullptr, nullptr, n);
    eler_kernel<<<(n + 7) / 8, 256>>>(a_l, a_r, n);

    // GAT aggregation + elu + residual + LN (emits lnv bf16 hi/lo)
    gat_ln_kernel<<<(n + 7) / 8, 256>>>(x, ln_g, ln_b, n);

    // FFN (HMMA)
    mgemm_kernel<128, 1><<<dim3(mblk, 4), 256, SMEM_SZ>>>(
        lnvhi, lnvlo, w1hi, w1lo, b1, nullptr, nullptr, inthi, intlo, n);
    mgemm_kernel<512, 2><<<dim3(mblk, 1), 256, SMEM_SZ>>>(
        inthi, intlo, w2hi, w2lo, b2, g_h_p, (float*)d_out, nullptr, nullptr, n);
}